// round 7
// baseline (speedup 1.0000x reference)
#include <cuda_runtime.h>
#include <math.h>

#define N 256
#define ND (N*N)
#define D 128
#define LAM 1e-3f
#define EPS 1e-3f

// ---- static scratch (no allocations allowed) ----
__device__ float g_z2s[N*D];
__device__ float g_X[N*2*D], g_Xs[N*2*D];
__device__ float g_n1[N], g_n2[N], g_n2s[N], g_nX[N], g_nXs[N];
__device__ float g_D1[ND], g_Dd[ND], g_Ddd[ND], g_DnA[ND], g_DnB[ND];
__device__ float g_Amat[8][ND];   // 0..3 denom A_s -> U (upper), 4..7 numerator
__device__ float g_Atr[8][ND];    // U^T for coalesced backward solve
__device__ float g_invd[8][N];
__device__ float g_Wm[4][ND];     // W_s[i,k]
__device__ float g_Mt[4][ND];     // row k = column k of M_s (RHS)
__device__ float g_bnum[4][N];
__device__ float g_Csol[4][ND];   // row k = column k of C_s = A^-1 M
__device__ float g_xnum[4][N];
__device__ float g_R[ND];
__device__ float g_denum[N];

__constant__ float c_inv2s2[4] = {0.5f, 5.0e-3f, 5.0e-5f, 5.0e-7f};

// 1. gather + squared norms
__global__ void k_gather(const float* __restrict__ z1, const float* __restrict__ z2,
                         const int* __restrict__ p1, const int* __restrict__ p2) {
    int i = blockIdx.x, t = threadIdx.x; // 128 threads
    float a  = z1[i*D+t],      b  = z2[i*D+t];
    float as = z1[p1[i]*D+t],  bs = z2[p2[i]*D+t];
    g_X [i*2*D+t] = a;  g_X [i*2*D+D+t] = b;
    g_Xs[i*2*D+t] = as; g_Xs[i*2*D+D+t] = bs;
    g_z2s[i*D+t] = bs;
    float v1=a*a, v2=b*b, v3=as*as, v4=bs*bs;
    #pragma unroll
    for (int o=16;o;o>>=1){
        v1+=__shfl_down_sync(~0u,v1,o); v2+=__shfl_down_sync(~0u,v2,o);
        v3+=__shfl_down_sync(~0u,v3,o); v4+=__shfl_down_sync(~0u,v4,o);
    }
    __shared__ float s1[4],s2[4],s3[4],s4[4];
    int w=t>>5;
    if(!(t&31)){s1[w]=v1;s2[w]=v2;s3[w]=v3;s4[w]=v4;}
    __syncthreads();
    if(t==0){
        float n1=s1[0]+s1[1]+s1[2]+s1[3], n2=s2[0]+s2[1]+s2[2]+s2[3];
        float n1s=s3[0]+s3[1]+s3[2]+s3[3], n2s=s4[0]+s4[1]+s4[2]+s4[3];
        g_n1[i]=n1; g_n2[i]=n2; g_n2s[i]=n2s; g_nX[i]=n1+n2; g_nXs[i]=n1s+n2s;
    }
}

// 2. five squared-distance matrices
__global__ void k_dist(const float* __restrict__ z1, const float* __restrict__ z2) {
    const float *A,*B,*na,*nb; float* out; int K;
    switch (blockIdx.z) {
        case 0:  A=z1;    B=z2;    na=g_n1;  nb=g_n2;  K=D;   out=g_D1;  break;
        case 1:  A=g_z2s; B=z2;    na=g_n2s; nb=g_n2;  K=D;   out=g_Dd;  break;
        case 2:  A=g_z2s; B=g_z2s; na=g_n2s; nb=g_n2s; K=D;   out=g_Ddd; break;
        case 3:  A=g_X;   B=g_X;   na=g_nX;  nb=g_nX;  K=2*D; out=g_DnA; break;
        default: A=g_X;   B=g_Xs;  na=g_nX;  nb=g_nXs; K=2*D; out=g_DnB; break;
    }
    __shared__ float As[32][33], Bs[32][33];
    int tx=threadIdx.x, ty=threadIdx.y;            // (32,32)
    int row=blockIdx.y*32+ty, col=blockIdx.x*32+tx;
    float acc=0.f;
    for (int kb=0; kb<K; kb+=32) {
        As[ty][tx]=A[row*K+kb+tx];
        Bs[ty][tx]=B[(blockIdx.x*32+ty)*K+kb+tx];
        __syncthreads();
        #pragma unroll
        for (int kk=0; kk<32; kk++) acc=fmaf(As[ty][kk],Bs[tx][kk],acc);
        __syncthreads();
    }
    out[row*N+col]=fmaxf(na[row]+nb[col]-2.f*acc,0.f);
}

// 3. kernel matrices per sigma
__global__ void k_build() {
    int r=blockIdx.x, s=blockIdx.y, t=threadIdx.x;  // block 256
    float c=c_inv2s2[s];
    float lam_d=(t==r)?LAM:0.f;
    g_Amat[s  ][r*N+t]=expf(-c*g_Ddd[r*N+t])+lam_d;
    g_Amat[4+s][r*N+t]=expf(-c*g_DnA[r*N+t])+lam_d;
    g_Wm[s][r*N+t]=expf(-c*g_D1[r*N+t]);
    g_Mt[s][t*N+r]=expf(-c*g_Dd[r*N+t]);        // RHS column t contiguous
    float e=expf(-c*g_DnB[r*N+t]);
    #pragma unroll
    for (int o=16;o;o>>=1) e+=__shfl_down_sync(~0u,e,o);
    __shared__ float sr[8];
    if(!(t&31)) sr[t>>5]=e;
    __syncthreads();
    if(t==0){ float s0=0.f;
        #pragma unroll
        for(int w=0;w<8;w++) s0+=sr[w];
        g_bnum[s][r]=s0; }
}

// 4. in-place Cholesky A = U^T U (upper), one block per matrix
__global__ void k_chol() {
    float* A=g_Amat[blockIdx.x];
    __shared__ float srow[N];
    __shared__ float sinv;
    int t=threadIdx.x, wid=t>>5, lane=t&31;          // block 256
    srow[t]=0.f;
    for (int k=0;k<N;k++) {
        __syncthreads();
        if(t==0){ float d=sqrtf(fmaxf(A[k*N+k],1e-30f)); A[k*N+k]=d; sinv=1.f/d; }
        __syncthreads();
        float inv=sinv;
        if(t>k){ float v=A[k*N+t]*inv; A[k*N+t]=v; srow[t]=v; }
        __syncthreads();
        int kb=(k+1)&~3;   // stale cols <=k only touch never-read lower triangle
        for (int i=k+1+wid;i<N;i+=8) {
            float ui=srow[i];
            for (int j=kb+lane*4;j<N;j+=128) {
                float4 s4=*reinterpret_cast<const float4*>(&srow[j]);
                float4 a =*reinterpret_cast<float4*>(&A[i*N+j]);
                a.x=fmaf(-ui,s4.x,a.x); a.y=fmaf(-ui,s4.y,a.y);
                a.z=fmaf(-ui,s4.z,a.z); a.w=fmaf(-ui,s4.w,a.w);
                *reinterpret_cast<float4*>(&A[i*N+j])=a;
            }
        }
    }
}

// 5. transpose U + inverse diagonal
__global__ void k_transpose() {
    __shared__ float tile[32][33];
    const float* A=g_Amat[blockIdx.z]; float* At=g_Atr[blockIdx.z];
    int tx=threadIdx.x, ty=threadIdx.y;              // (32,8)
    int x0=blockIdx.x*32, y0=blockIdx.y*32;
    #pragma unroll
    for(int i=0;i<32;i+=8) tile[ty+i][tx]=A[(y0+ty+i)*N+x0+tx];
    __syncthreads();
    #pragma unroll
    for(int i=0;i<32;i+=8) At[(x0+ty+i)*N+y0+tx]=tile[tx][ty+i];
}
__global__ void k_invd() {
    g_invd[blockIdx.x][threadIdx.x]=1.f/g_Amat[blockIdx.x][threadIdx.x*N+threadIdx.x];
}

// 6. fused forward (U^T y=b) + backward (U x=y), one warp per RHS column
__global__ void k_trsm() {
    __shared__ float xs[8][N];
    int s=blockIdx.y, t=threadIdx.x, wid=t>>5, lane=t&31;  // block 256
    const float *U,*L,*invd,*src; float* dst;
    if (blockIdx.x<32) {
        int col=blockIdx.x*8+wid;
        U=g_Amat[s]; L=g_Atr[s]; invd=g_invd[s];
        src=&g_Mt[s][col*N]; dst=&g_Csol[s][col*N];
    } else {
        if (wid!=0) return;
        U=g_Amat[4+s]; L=g_Atr[4+s]; invd=g_invd[4+s];
        src=g_bnum[s]; dst=g_xnum[s];
    }
    float* x=xs[wid];
    for(int j=lane;j<N;j+=32) x[j]=src[j];
    __syncwarp();
    for (int k=0;k<N;k++) {                 // forward: reads U row k (coalesced)
        float xk=0.f;
        if(lane==0){ xk=x[k]*invd[k]; x[k]=xk; }
        xk=__shfl_sync(~0u,xk,0);
        for(int j=k+1+lane;j<N;j+=32) x[j]=fmaf(-U[k*N+j],xk,x[j]);
        __syncwarp();
    }
    for (int k=N-1;k>=0;k--) {              // backward: reads U^T row k (coalesced)
        float xk=0.f;
        if(lane==0){ xk=x[k]*invd[k]; x[k]=xk; }
        xk=__shfl_sync(~0u,xk,0);
        for(int j=lane;j<k;j+=32) x[j]=fmaf(-L[k*N+j],xk,x[j]);
        __syncwarp();
    }
    for(int j=lane;j<N;j+=32) dst[j]=x[j];
}

// 7. R = sum_s W_s * Csol_s (Csol rows = C^T rows), 32x32 tile, 2x2 micro
__global__ void k_gemmR() {
    __shared__ float Wa[32][33], Cb[32][33];
    int t=threadIdx.x;                                // block 256
    int tx=t&15, ty=t>>4;
    int rb=blockIdx.y*32, cb=blockIdx.x*32;
    int lr=t>>5, lc=t&31;                             // tile loader coords
    float a00=0.f,a01=0.f,a10=0.f,a11=0.f;
    for (int s=0;s<4;s++) {
        const float* Wp=g_Wm[s]; const float* Cp=g_Csol[s];
        for (int kb=0;kb<N;kb+=32) {
            __syncthreads();
            #pragma unroll
            for(int i=0;i<32;i+=8){
                Wa[lr+i][lc]=Wp[(rb+lr+i)*N+kb+lc];
                Cb[lr+i][lc]=Cp[(kb+lr+i)*N+cb+lc];
            }
            __syncthreads();
            #pragma unroll
            for (int kk=0;kk<32;kk++) {
                float w0=Wa[ty][kk], w1=Wa[ty+16][kk];
                float c0=Cb[kk][tx], c1=Cb[kk][tx+16];
                a00=fmaf(w0,c0,a00); a01=fmaf(w0,c1,a01);
                a10=fmaf(w1,c0,a10); a11=fmaf(w1,c1,a11);
            }
        }
    }
    g_R[(rb+ty   )*N+cb+tx   ]=a00;
    g_R[(rb+ty   )*N+cb+tx+16]=a01;
    g_R[(rb+ty+16)*N+cb+tx   ]=a10;
    g_R[(rb+ty+16)*N+cb+tx+16]=a11;
}

// 8. denum_i = 0.25*sum_j relu(R[i,j]) + N*eps
__global__ void k_rowsum() {
    int i=blockIdx.x, t=threadIdx.x;                  // block 256
    float v=fmaxf(g_R[i*N+t],0.f);
    #pragma unroll
    for(int o=16;o;o>>=1) v+=__shfl_down_sync(~0u,v,o);
    __shared__ float sr[8];
    if(!(t&31)) sr[t>>5]=v;
    __syncthreads();
    if(t==0){ float s0=0.f;
        #pragma unroll
        for(int w=0;w<8;w++) s0+=sr[w];
        g_denum[i]=0.25f*s0+(float)N*EPS; }
}

// 9. loss = sum_i log(denum_i) + log(relu(avg xnum)+eps)
__global__ void k_loss(float* __restrict__ out) {
    int t=threadIdx.x;                                 // block 256
    float est=fmaxf(0.25f*(g_xnum[0][t]+g_xnum[1][t]+g_xnum[2][t]+g_xnum[3][t]),0.f)+EPS;
    float v=logf(g_denum[t])+logf(est);
    #pragma unroll
    for(int o=16;o;o>>=1) v+=__shfl_down_sync(~0u,v,o);
    __shared__ float sr[8];
    if(!(t&31)) sr[t>>5]=v;
    __syncthreads();
    if(t==0){ float s0=0.f;
        #pragma unroll
        for(int w=0;w<8;w++) s0+=sr[w];
        out[0]=s0; }
}

extern "C" void kernel_launch(void* const* d_in, const int* in_sizes, int n_in,
                              void* d_out, int out_size) {
    const float* z1=(const float*)d_in[0];
    const float* z2=(const float*)d_in[1];
    const int*   p1=(const int*)d_in[2];
    const int*   p2=(const int*)d_in[3];
    float* out=(float*)d_out;

    k_gather<<<N,128>>>(z1,z2,p1,p2);
    k_dist<<<dim3(8,8,5),dim3(32,32)>>>(z1,z2);
    k_build<<<dim3(N,4),N>>>();
    k_chol<<<8,256>>>();
    k_transpose<<<dim3(8,8,8),dim3(32,8)>>>();
    k_invd<<<8,N>>>();
    k_trsm<<<dim3(33,4),256>>>();
    k_gemmR<<<dim3(8,8),256>>>();
    k_rowsum<<<N,N>>>();
    k_loss<<<1,N>>>(out);
}

// round 8
// speedup vs baseline: 4.4959x; 4.4959x over previous
#include <cuda_runtime.h>
#include <math.h>

#define N 256
#define ND (N*N)
#define D 128
#define PB 32
#define LAM 1e-3f
#define EPS 1e-3f

// ---- static scratch ----
__device__ float g_z2s[N*D];
__device__ float g_X[N*2*D], g_Xs[N*2*D];
__device__ float g_n1[N], g_n2[N], g_n2s[N], g_nX[N], g_nXs[N];
__device__ float g_D1[ND], g_Dd[ND], g_Ddd[ND], g_DnA[ND], g_DnB[ND];
__device__ float g_Amat[8][ND];   // 0..3 denom A_s -> U (upper), 4..7 numerator
__device__ float g_Atr[8][ND];    // U^T rows (for backward solve)
__device__ float g_invd[8][N];
__device__ float g_Wm[4][ND];
__device__ float g_Mt[4][ND];     // row k = RHS column k of M_s
__device__ float g_bnum[4][N];
__device__ float g_Csol[4][ND];   // row k = solution column k
__device__ float g_xnum[4][N];
__device__ float g_R[ND];
__device__ float g_denum[N];

__constant__ float c_inv2s2[4] = {0.5f, 5.0e-3f, 5.0e-5f, 5.0e-7f};

// ---------- 1. gather + norms ----------
__global__ void k_gather(const float* __restrict__ z1, const float* __restrict__ z2,
                         const int* __restrict__ p1, const int* __restrict__ p2) {
    int i = blockIdx.x, t = threadIdx.x; // 128
    float a  = z1[i*D+t],      b  = z2[i*D+t];
    float as = z1[p1[i]*D+t],  bs = z2[p2[i]*D+t];
    g_X [i*2*D+t] = a;  g_X [i*2*D+D+t] = b;
    g_Xs[i*2*D+t] = as; g_Xs[i*2*D+D+t] = bs;
    g_z2s[i*D+t] = bs;
    float v1=a*a, v2=b*b, v3=as*as, v4=bs*bs;
    #pragma unroll
    for (int o=16;o;o>>=1){
        v1+=__shfl_down_sync(~0u,v1,o); v2+=__shfl_down_sync(~0u,v2,o);
        v3+=__shfl_down_sync(~0u,v3,o); v4+=__shfl_down_sync(~0u,v4,o);
    }
    __shared__ float s1[4],s2[4],s3[4],s4[4];
    int w=t>>5;
    if(!(t&31)){s1[w]=v1;s2[w]=v2;s3[w]=v3;s4[w]=v4;}
    __syncthreads();
    if(t==0){
        float n1=s1[0]+s1[1]+s1[2]+s1[3], n2=s2[0]+s2[1]+s2[2]+s2[3];
        float n1s=s3[0]+s3[1]+s3[2]+s3[3], n2s=s4[0]+s4[1]+s4[2]+s4[3];
        g_n1[i]=n1; g_n2[i]=n2; g_n2s[i]=n2s; g_nX[i]=n1+n2; g_nXs[i]=n1s+n2s;
    }
}

// ---------- 2. five squared-distance matrices ----------
__global__ void k_dist(const float* __restrict__ z1, const float* __restrict__ z2) {
    const float *A,*B,*na,*nb; float* out; int K;
    switch (blockIdx.z) {
        case 0:  A=z1;    B=z2;    na=g_n1;  nb=g_n2;  K=D;   out=g_D1;  break;
        case 1:  A=g_z2s; B=z2;    na=g_n2s; nb=g_n2;  K=D;   out=g_Dd;  break;
        case 2:  A=g_z2s; B=g_z2s; na=g_n2s; nb=g_n2s; K=D;   out=g_Ddd; break;
        case 3:  A=g_X;   B=g_X;   na=g_nX;  nb=g_nX;  K=2*D; out=g_DnA; break;
        default: A=g_X;   B=g_Xs;  na=g_nX;  nb=g_nXs; K=2*D; out=g_DnB; break;
    }
    __shared__ float As[32][33], Bs[32][33];
    int tx=threadIdx.x, ty=threadIdx.y;
    int row=blockIdx.y*32+ty, col=blockIdx.x*32+tx;
    float acc=0.f;
    for (int kb=0; kb<K; kb+=32) {
        As[ty][tx]=A[row*K+kb+tx];
        Bs[ty][tx]=B[(blockIdx.x*32+ty)*K+kb+tx];
        __syncthreads();
        #pragma unroll
        for (int kk=0; kk<32; kk++) acc=fmaf(As[ty][kk],Bs[tx][kk],acc);
        __syncthreads();
    }
    out[row*N+col]=fmaxf(na[row]+nb[col]-2.f*acc,0.f);
}

// ---------- 3. kernel matrices ----------
__global__ void k_build() {
    int r=blockIdx.x, s=blockIdx.y, t=threadIdx.x;  // block 256
    float c=c_inv2s2[s];
    float lam_d=(t==r)?LAM:0.f;
    g_Amat[s  ][r*N+t]=expf(-c*g_Ddd[r*N+t])+lam_d;
    g_Amat[4+s][r*N+t]=expf(-c*g_DnA[r*N+t])+lam_d;
    g_Wm[s][r*N+t]=expf(-c*g_D1[r*N+t]);
    g_Mt[s][t*N+r]=expf(-c*g_Dd[r*N+t]);
    float e=expf(-c*g_DnB[r*N+t]);
    #pragma unroll
    for (int o=16;o;o>>=1) e+=__shfl_down_sync(~0u,e,o);
    __shared__ float sr[8];
    if(!(t&31)) sr[t>>5]=e;
    __syncthreads();
    if(t==0){ float s0=0.f;
        #pragma unroll
        for(int w=0;w<8;w++) s0+=sr[w];
        g_bnum[s][r]=s0; }
}

// ---------- 4. LEFT-LOOKING Cholesky, panel in smem, streamed update ----------
__global__ void __launch_bounds__(512) k_chol() {
    int m = blockIdx.x;
    float* A = g_Amat[m];
    __shared__ float P[PB][N];         // 32KB panel (local cols 0..ncols-1 = global pb..N-1)
    __shared__ float Ub[PB][PB+1];
    __shared__ float sdinv;
    int tid = threadIdx.x;
    int jj = tid & 255, half = tid >> 8;   // half in {0,1}: rows [half*16, half*16+16)

    for (int pb = 0; pb < N; pb += PB) {
        int ncols = N - pb;
        bool colok = jj < ncols;
        int j = pb + jj;
        float acc[16];
        if (colok) {
            #pragma unroll
            for (int r=0;r<16;r++) acc[r] = A[(pb+half*16+r)*N + j];
        }
        // apply all previous panels: acc -= sum_k U[k][pb+row]*U[k][j]
        for (int kb = 0; kb < pb; kb += PB) {
            __syncthreads();
            { // load Ub[kk][rr] = U[kb+kk][pb+rr], 32x32, 512 threads x 2 elems
                int kk = tid >> 4, rr = tid & 15;
                Ub[kk][rr]    = A[(kb+kk)*N + pb + rr];
                Ub[kk][rr+16] = A[(kb+kk)*N + pb + rr + 16];
            }
            __syncthreads();
            if (colok) {
                #pragma unroll 4
                for (int kk=0; kk<PB; kk++) {
                    float ukj = A[(kb+kk)*N + j];
                    #pragma unroll
                    for (int r=0;r<16;r++)
                        acc[r] = fmaf(-Ub[kk][half*16+r], ukj, acc[r]);
                }
            }
        }
        __syncthreads();
        if (colok) {
            #pragma unroll
            for (int r=0;r<16;r++) P[half*16+r][jj] = acc[r];
        }
        __syncthreads();
        // factor 32 x ncols trapezoid in smem
        for (int k=0;k<PB;k++) {
            if (tid==0) {
                float d = sqrtf(fmaxf(P[k][k],1e-30f));
                P[k][k]=d; sdinv = 1.f/d;
                g_invd[m][pb+k] = 1.f/d;
            }
            __syncthreads();
            float inv = sdinv;
            if (tid > k && tid < ncols) P[k][tid] *= inv;
            __syncthreads();
            {
                int j2 = tid & 255, h2 = tid >> 8;
                if (j2 > k && j2 < ncols) {
                    float pk = P[k][j2];
                    #pragma unroll
                    for (int i = 0; i < 16; i++) {
                        int row = h2*16 + i;
                        if (row > k) P[row][j2] = fmaf(-P[k][row], pk, P[row][j2]);
                    }
                }
            }
            __syncthreads();
        }
        // write back
        for (int e = tid; e < PB*ncols; e += 512) {
            int r = e / ncols, c = e - r*ncols;
            A[(pb+r)*N + pb + c] = P[r][c];
        }
        __syncthreads();
    }
}

// ---------- 5. transpose U ----------
__global__ void k_transpose() {
    __shared__ float tile[32][33];
    const float* A=g_Amat[blockIdx.z]; float* At=g_Atr[blockIdx.z];
    int tx=threadIdx.x, ty=threadIdx.y;              // (32,8)
    int x0=blockIdx.x*32, y0=blockIdx.y*32;
    #pragma unroll
    for(int i=0;i<32;i+=8) tile[ty+i][tx]=A[(y0+ty+i)*N+x0+tx];
    __syncthreads();
    #pragma unroll
    for(int i=0;i<32;i+=8) At[(x0+ty+i)*N+y0+tx]=tile[tx][ty+i];
}

// ---------- 6. register-resident TRSM, warp per column, 4-deep prefetch ----------
__global__ void __launch_bounds__(256) k_trsm() {
    int s=blockIdx.y, t=threadIdx.x, wid=t>>5, lane=t&31;
    const float *U,*L,*invd,*src; float* dst;
    if (blockIdx.x<32) {
        int col=blockIdx.x*8+wid;
        U=g_Amat[s]; L=g_Atr[s]; invd=g_invd[s];
        src=&g_Mt[s][col*N]; dst=&g_Csol[s][col*N];
    } else {
        if (wid) return;
        U=g_Amat[4+s]; L=g_Atr[4+s]; invd=g_invd[4+s];
        src=g_bnum[s]; dst=g_xnum[s];
    }
    float x[8], iv[8];
    #pragma unroll
    for (int r=0;r<8;r++){ x[r]=src[r*32+lane]; iv[r]=invd[r*32+lane]; }

    float ub[4][8];
    // ======== forward: L x = b with L = U^T, column-sweep reading U rows ========
    #pragma unroll
    for (int q=0;q<4;q++)
        #pragma unroll
        for (int r=0;r<8;r++) ub[q][r]=U[q*N + r*32 + lane];

    #pragma unroll
    for (int kr=0;kr<8;kr++) {
        #pragma unroll 1
        for (int kl4=0; kl4<32; kl4+=4) {
            #pragma unroll
            for (int q=0;q<4;q++) {
                int kl = kl4 + q;
                int k  = kr*32 + kl;
                float v = x[kr]*iv[kr];
                float xk = __shfl_sync(~0u, v, kl);
                if (lane==kl) x[kr]=xk;
                #pragma unroll
                for (int r=kr;r<8;r++) {
                    bool act = (r>kr) || (lane>kl);
                    float nx = fmaf(-ub[q][r], xk, x[r]);
                    x[r] = act ? nx : x[r];
                }
                int kn = k+4;
                if (kn < N) {
                    #pragma unroll
                    for (int r=0;r<8;r++) ub[q][r] = U[kn*N + r*32 + lane];
                }
            }
        }
    }
    // ======== backward: U x = y, reading U^T rows (g_Atr) ========
    #pragma unroll
    for (int q=0;q<4;q++)
        #pragma unroll
        for (int r=0;r<8;r++) ub[q][r]=L[(N-4+q)*N + r*32 + lane];

    #pragma unroll
    for (int kr=7;kr>=0;kr--) {
        #pragma unroll 1
        for (int kl4=28; kl4>=0; kl4-=4) {
            #pragma unroll
            for (int q=3;q>=0;q--) {
                int kl = kl4 + q;
                int k  = kr*32 + kl;
                float v = x[kr]*iv[kr];
                float xk = __shfl_sync(~0u, v, kl);
                if (lane==kl) x[kr]=xk;
                #pragma unroll
                for (int r=0;r<=kr;r++) {
                    bool act = (r<kr) || (lane<kl);
                    float nx = fmaf(-ub[q][r], xk, x[r]);
                    x[r] = act ? nx : x[r];
                }
                int kn = k-4;
                if (kn >= 0) {
                    #pragma unroll
                    for (int r=0;r<8;r++) ub[q][r] = L[kn*N + r*32 + lane];
                }
            }
        }
    }
    #pragma unroll
    for (int r=0;r<8;r++) dst[r*32+lane] = x[r];
}

// ---------- 7. R = sum_s W_s * C_s^T ----------
__global__ void k_gemmR() {
    __shared__ float Wa[32][33], Cb[32][33];
    int t=threadIdx.x;                                // 256
    int tx=t&15, ty=t>>4;
    int rb=blockIdx.y*32, cb=blockIdx.x*32;
    int lr=t>>5, lc=t&31;
    float a00=0.f,a01=0.f,a10=0.f,a11=0.f;
    for (int s=0;s<4;s++) {
        const float* Wp=g_Wm[s]; const float* Cp=g_Csol[s];
        for (int kb=0;kb<N;kb+=32) {
            __syncthreads();
            #pragma unroll
            for(int i=0;i<32;i+=8){
                Wa[lr+i][lc]=Wp[(rb+lr+i)*N+kb+lc];
                Cb[lr+i][lc]=Cp[(cb+lr+i)*N+kb+lc];   // Cb[j'][k'] = Csol[cb+j'][kb+k']
            }
            __syncthreads();
            #pragma unroll
            for (int kk=0;kk<32;kk++) {
                float w0=Wa[ty][kk], w1=Wa[ty+16][kk];
                float c0=Cb[tx][kk], c1=Cb[tx+16][kk];
                a00=fmaf(w0,c0,a00); a01=fmaf(w0,c1,a01);
                a10=fmaf(w1,c0,a10); a11=fmaf(w1,c1,a11);
            }
        }
    }
    g_R[(rb+ty   )*N+cb+tx   ]=a00;
    g_R[(rb+ty   )*N+cb+tx+16]=a01;
    g_R[(rb+ty+16)*N+cb+tx   ]=a10;
    g_R[(rb+ty+16)*N+cb+tx+16]=a11;
}

// ---------- 8. row sums ----------
__global__ void k_rowsum() {
    int i=blockIdx.x, t=threadIdx.x;
    float v=fmaxf(g_R[i*N+t],0.f);
    #pragma unroll
    for(int o=16;o;o>>=1) v+=__shfl_down_sync(~0u,v,o);
    __shared__ float sr[8];
    if(!(t&31)) sr[t>>5]=v;
    __syncthreads();
    if(t==0){ float s0=0.f;
        #pragma unroll
        for(int w=0;w<8;w++) s0+=sr[w];
        g_denum[i]=0.25f*s0+(float)N*EPS; }
}

// ---------- 9. loss ----------
__global__ void k_loss(float* __restrict__ out) {
    int t=threadIdx.x;
    float est=fmaxf(0.25f*(g_xnum[0][t]+g_xnum[1][t]+g_xnum[2][t]+g_xnum[3][t]),0.f)+EPS;
    float v=logf(g_denum[t])+logf(est);
    #pragma unroll
    for(int o=16;o;o>>=1) v+=__shfl_down_sync(~0u,v,o);
    __shared__ float sr[8];
    if(!(t&31)) sr[t>>5]=v;
    __syncthreads();
    if(t==0){ float s0=0.f;
        #pragma unroll
        for(int w=0;w<8;w++) s0+=sr[w];
        out[0]=s0; }
}

extern "C" void kernel_launch(void* const* d_in, const int* in_sizes, int n_in,
                              void* d_out, int out_size) {
    const float* z1=(const float*)d_in[0];
    const float* z2=(const float*)d_in[1];
    const int*   p1=(const int*)d_in[2];
    const int*   p2=(const int*)d_in[3];
    float* out=(float*)d_out;

    k_gather<<<N,128>>>(z1,z2,p1,p2);
    k_dist<<<dim3(8,8,5),dim3(32,32)>>>(z1,z2);
    k_build<<<dim3(N,4),N>>>();
    k_chol<<<8,512>>>();
    k_transpose<<<dim3(8,8,8),dim3(32,8)>>>();
    k_trsm<<<dim3(33,4),256>>>();
    k_gemmR<<<dim3(8,8),256>>>();
    k_rowsum<<<N,N>>>();
    k_loss<<<1,N>>>(out);
}

// round 9
// speedup vs baseline: 7.1424x; 1.5887x over previous
#include <cuda_runtime.h>
#include <math.h>

#define N 256
#define ND (N*N)
#define D 128
#define LAM 1e-3f
#define EPS 1e-3f

// ---- static scratch ----
__device__ float g_z2s[N*D];
__device__ float g_X[N*2*D], g_Xs[N*2*D];
__device__ float g_n1[N], g_n2[N], g_n2s[N], g_nX[N], g_nXs[N];
__device__ float g_D1[ND], g_Dd[ND], g_Ddd[ND], g_DnA[ND], g_DnB[ND];
__device__ float g_Amat[8][ND];   // 0..3 denom A_s -> U (upper), 4..7 numerator
__device__ float g_Atr[8][ND];    // U^T rows (for backward solve)
__device__ float g_invd[8][N];
__device__ float g_Wm[4][ND];
__device__ float g_Mt[4][ND];     // row k = RHS column k of M_s
__device__ float g_bnum[4][N];
__device__ float g_Csol[4][ND];   // row k = solution column k
__device__ float g_xnum[4][N];
__device__ float g_R[ND];
__device__ float g_denum[N];

__constant__ float c_inv2s2[4] = {0.5f, 5.0e-3f, 5.0e-5f, 5.0e-7f};

// ---------- 1. gather + norms ----------
__global__ void k_gather(const float* __restrict__ z1, const float* __restrict__ z2,
                         const int* __restrict__ p1, const int* __restrict__ p2) {
    int i = blockIdx.x, t = threadIdx.x; // 128
    float a  = z1[i*D+t],      b  = z2[i*D+t];
    float as = z1[p1[i]*D+t],  bs = z2[p2[i]*D+t];
    g_X [i*2*D+t] = a;  g_X [i*2*D+D+t] = b;
    g_Xs[i*2*D+t] = as; g_Xs[i*2*D+D+t] = bs;
    g_z2s[i*D+t] = bs;
    float v1=a*a, v2=b*b, v3=as*as, v4=bs*bs;
    #pragma unroll
    for (int o=16;o;o>>=1){
        v1+=__shfl_down_sync(~0u,v1,o); v2+=__shfl_down_sync(~0u,v2,o);
        v3+=__shfl_down_sync(~0u,v3,o); v4+=__shfl_down_sync(~0u,v4,o);
    }
    __shared__ float s1[4],s2[4],s3[4],s4[4];
    int w=t>>5;
    if(!(t&31)){s1[w]=v1;s2[w]=v2;s3[w]=v3;s4[w]=v4;}
    __syncthreads();
    if(t==0){
        float n1=s1[0]+s1[1]+s1[2]+s1[3], n2=s2[0]+s2[1]+s2[2]+s2[3];
        float n1s=s3[0]+s3[1]+s3[2]+s3[3], n2s=s4[0]+s4[1]+s4[2]+s4[3];
        g_n1[i]=n1; g_n2[i]=n2; g_n2s[i]=n2s; g_nX[i]=n1+n2; g_nXs[i]=n1s+n2s;
    }
}

// ---------- 2. five squared-distance matrices ----------
__global__ void k_dist(const float* __restrict__ z1, const float* __restrict__ z2) {
    const float *A,*B,*na,*nb; float* out; int K;
    switch (blockIdx.z) {
        case 0:  A=z1;    B=z2;    na=g_n1;  nb=g_n2;  K=D;   out=g_D1;  break;
        case 1:  A=g_z2s; B=z2;    na=g_n2s; nb=g_n2;  K=D;   out=g_Dd;  break;
        case 2:  A=g_z2s; B=g_z2s; na=g_n2s; nb=g_n2s; K=D;   out=g_Ddd; break;
        case 3:  A=g_X;   B=g_X;   na=g_nX;  nb=g_nX;  K=2*D; out=g_DnA; break;
        default: A=g_X;   B=g_Xs;  na=g_nX;  nb=g_nXs; K=2*D; out=g_DnB; break;
    }
    __shared__ float As[32][33], Bs[32][33];
    int tx=threadIdx.x, ty=threadIdx.y;
    int row=blockIdx.y*32+ty, col=blockIdx.x*32+tx;
    float acc=0.f;
    for (int kb=0; kb<K; kb+=32) {
        As[ty][tx]=A[row*K+kb+tx];
        Bs[ty][tx]=B[(blockIdx.x*32+ty)*K+kb+tx];
        __syncthreads();
        #pragma unroll
        for (int kk=0; kk<32; kk++) acc=fmaf(As[ty][kk],Bs[tx][kk],acc);
        __syncthreads();
    }
    out[row*N+col]=fmaxf(na[row]+nb[col]-2.f*acc,0.f);
}

// ---------- 3. kernel matrices ----------
__global__ void k_build() {
    int r=blockIdx.x, s=blockIdx.y, t=threadIdx.x;  // block 256
    float c=c_inv2s2[s];
    float lam_d=(t==r)?LAM:0.f;
    g_Amat[s  ][r*N+t]=expf(-c*g_Ddd[r*N+t])+lam_d;
    g_Amat[4+s][r*N+t]=expf(-c*g_DnA[r*N+t])+lam_d;
    g_Wm[s][r*N+t]=expf(-c*g_D1[r*N+t]);
    g_Mt[s][t*N+r]=expf(-c*g_Dd[r*N+t]);
    float e=expf(-c*g_DnB[r*N+t]);
    #pragma unroll
    for (int o=16;o;o>>=1) e+=__shfl_down_sync(~0u,e,o);
    __shared__ float sr[8];
    if(!(t&31)) sr[t>>5]=e;
    __syncthreads();
    if(t==0){ float s0=0.f;
        #pragma unroll
        for(int w=0;w<8;w++) s0+=sr[w];
        g_bnum[s][r]=s0; }
}

// ---------- 4a. warp-register 32x32 Cholesky on smem block ----------
__device__ __forceinline__ void factor32(float (*Ub)[65], int o, float* sinv, int lane) {
    float r[32];
    #pragma unroll
    for (int i=0;i<32;i++) r[i]=Ub[o+i][o+lane];
    #pragma unroll
    for (int k=0;k<32;k++) {
        float v = __shfl_sync(0xffffffffu, r[k], k);
        float inv = rsqrtf(fmaxf(v, 1e-30f));
        if (lane == k) { r[k] = v * inv; sinv[o+k] = inv; }
        else if (lane > k) r[k] *= inv;
        #pragma unroll
        for (int i=k+1;i<32;i++) {
            float u = __shfl_sync(0xffffffffu, r[k], i);
            if (lane >= i) r[i] = fmaf(-u, r[k], r[i]);
        }
    }
    #pragma unroll
    for (int i=0;i<32;i++) Ub[o+i][o+lane]=r[i];
}

// ---------- 4b. panel: factor 64x64 diag + TRSM of row panel ----------
__global__ void __launch_bounds__(512) k_panel(int pb) {
    int m = blockIdx.x;
    float* A = g_Amat[m];
    __shared__ float Ub[64][65];
    __shared__ float sinv[64];
    int tid = threadIdx.x;

    for (int e=tid; e<64*64; e+=512) {
        int r=e>>6, c=e&63;
        Ub[r][c]=A[(pb+r)*N + pb + c];
    }
    __syncthreads();

    if (tid < 32) factor32(Ub, 0, sinv, tid);
    __syncthreads();

    if (tid < 32) {                 // TRSM inner 32 cols of diag block
        float x[32];
        #pragma unroll
        for (int i=0;i<32;i++) x[i]=Ub[i][32+tid];
        #pragma unroll
        for (int k=0;k<32;k++) {
            x[k]*=sinv[k];
            #pragma unroll
            for (int i=k+1;i<32;i++) x[i]=fmaf(-Ub[k][i],x[k],x[i]);
        }
        #pragma unroll
        for (int i=0;i<32;i++) Ub[i][32+tid]=x[i];
    }
    __syncthreads();

    for (int e=tid; e<1024; e+=512) {    // A22 -= U12^T U12 (within diag block)
        int i=e>>5, j=e&31;
        float acc=Ub[32+i][32+j];
        #pragma unroll
        for (int k=0;k<32;k++) acc=fmaf(-Ub[k][32+i],Ub[k][32+j],acc);
        Ub[32+i][32+j]=acc;
    }
    __syncthreads();

    if (tid < 32) factor32(Ub, 32, sinv, tid);
    __syncthreads();

    for (int e=tid; e<64*64; e+=512) {   // write factored diag block back
        int r=e>>6, c=e&63;
        A[(pb+r)*N + pb + c]=Ub[r][c];
    }
    if (tid < 64) g_invd[m][pb+tid]=sinv[tid];

    // off-diag TRSM: U12 = U11^{-T} A12, thread per column
    int j = pb + 64 + tid;
    if (j < N) {
        float x[64];
        #pragma unroll
        for (int i=0;i<64;i++) x[i]=A[(pb+i)*N + j];
        #pragma unroll
        for (int k=0;k<64;k++) {
            x[k]*=sinv[k];
            #pragma unroll
            for (int i=k+1;i<64;i++) x[i]=fmaf(-Ub[k][i],x[k],x[i]);
        }
        #pragma unroll
        for (int i=0;i<64;i++) A[(pb+i)*N + j]=x[i];
    }
}

// ---------- 4c. trailing syrk: A22 -= U12^T U12, full-chip ----------
__global__ void __launch_bounds__(256) k_syrk(int pb) {
    if ((int)blockIdx.y > (int)blockIdx.x) return;   // upper tiles only
    float* A = g_Amat[blockIdx.z];
    int i0 = pb + 64 + blockIdx.y*32, j0 = pb + 64 + blockIdx.x*32;
    __shared__ float Ua[64][33], Vb[64][33];
    int t=threadIdx.x, tx=t&15, ty=t>>4;
    int lr=t>>5, lc=t&31;
    #pragma unroll
    for (int i=0;i<64;i+=8) {
        Ua[lr+i][lc]=A[(pb+lr+i)*N + i0 + lc];
        Vb[lr+i][lc]=A[(pb+lr+i)*N + j0 + lc];
    }
    __syncthreads();
    float a00=0.f,a01=0.f,a10=0.f,a11=0.f;
    #pragma unroll
    for (int k=0;k<64;k++) {
        float w0=Ua[k][ty], w1=Ua[k][ty+16];
        float c0=Vb[k][tx], c1=Vb[k][tx+16];
        a00=fmaf(w0,c0,a00); a01=fmaf(w0,c1,a01);
        a10=fmaf(w1,c0,a10); a11=fmaf(w1,c1,a11);
    }
    A[(i0+ty   )*N + j0+tx   ] -= a00;
    A[(i0+ty   )*N + j0+tx+16] -= a01;
    A[(i0+ty+16)*N + j0+tx   ] -= a10;
    A[(i0+ty+16)*N + j0+tx+16] -= a11;
}

// ---------- 5. transpose U ----------
__global__ void k_transpose() {
    __shared__ float tile[32][33];
    const float* A=g_Amat[blockIdx.z]; float* At=g_Atr[blockIdx.z];
    int tx=threadIdx.x, ty=threadIdx.y;              // (32,8)
    int x0=blockIdx.x*32, y0=blockIdx.y*32;
    #pragma unroll
    for(int i=0;i<32;i+=8) tile[ty+i][tx]=A[(y0+ty+i)*N+x0+tx];
    __syncthreads();
    #pragma unroll
    for(int i=0;i<32;i+=8) At[(x0+ty+i)*N+y0+tx]=tile[tx][ty+i];
}

// ---------- 6. register-resident TRSM, warp per column, 4-deep prefetch ----------
__global__ void __launch_bounds__(256) k_trsm() {
    int s=blockIdx.y, t=threadIdx.x, wid=t>>5, lane=t&31;
    const float *U,*L,*invd,*src; float* dst;
    if (blockIdx.x<32) {
        int col=blockIdx.x*8+wid;
        U=g_Amat[s]; L=g_Atr[s]; invd=g_invd[s];
        src=&g_Mt[s][col*N]; dst=&g_Csol[s][col*N];
    } else {
        if (wid) return;
        U=g_Amat[4+s]; L=g_Atr[4+s]; invd=g_invd[4+s];
        src=g_bnum[s]; dst=g_xnum[s];
    }
    float x[8], iv[8];
    #pragma unroll
    for (int r=0;r<8;r++){ x[r]=src[r*32+lane]; iv[r]=invd[r*32+lane]; }

    float ub[4][8];
    #pragma unroll
    for (int q=0;q<4;q++)
        #pragma unroll
        for (int r=0;r<8;r++) ub[q][r]=U[q*N + r*32 + lane];

    #pragma unroll
    for (int kr=0;kr<8;kr++) {
        #pragma unroll 1
        for (int kl4=0; kl4<32; kl4+=4) {
            #pragma unroll
            for (int q=0;q<4;q++) {
                int kl = kl4 + q;
                int k  = kr*32 + kl;
                float v = x[kr]*iv[kr];
                float xk = __shfl_sync(~0u, v, kl);
                if (lane==kl) x[kr]=xk;
                #pragma unroll
                for (int r=kr;r<8;r++) {
                    bool act = (r>kr) || (lane>kl);
                    float nx = fmaf(-ub[q][r], xk, x[r]);
                    x[r] = act ? nx : x[r];
                }
                int kn = k+4;
                if (kn < N) {
                    #pragma unroll
                    for (int r=0;r<8;r++) ub[q][r] = U[kn*N + r*32 + lane];
                }
            }
        }
    }
    #pragma unroll
    for (int q=0;q<4;q++)
        #pragma unroll
        for (int r=0;r<8;r++) ub[q][r]=L[(N-4+q)*N + r*32 + lane];

    #pragma unroll
    for (int kr=7;kr>=0;kr--) {
        #pragma unroll 1
        for (int kl4=28; kl4>=0; kl4-=4) {
            #pragma unroll
            for (int q=3;q>=0;q--) {
                int kl = kl4 + q;
                int k  = kr*32 + kl;
                float v = x[kr]*iv[kr];
                float xk = __shfl_sync(~0u, v, kl);
                if (lane==kl) x[kr]=xk;
                #pragma unroll
                for (int r=0;r<=kr;r++) {
                    bool act = (r<kr) || (lane<kl);
                    float nx = fmaf(-ub[q][r], xk, x[r]);
                    x[r] = act ? nx : x[r];
                }
                int kn = k-4;
                if (kn >= 0) {
                    #pragma unroll
                    for (int r=0;r<8;r++) ub[q][r] = L[kn*N + r*32 + lane];
                }
            }
        }
    }
    #pragma unroll
    for (int r=0;r<8;r++) dst[r*32+lane] = x[r];
}

// ---------- 7. R = sum_s W_s * C_s^T ----------
__global__ void k_gemmR() {
    __shared__ float Wa[32][33], Cb[32][33];
    int t=threadIdx.x;                                // 256
    int tx=t&15, ty=t>>4;
    int rb=blockIdx.y*32, cb=blockIdx.x*32;
    int lr=t>>5, lc=t&31;
    float a00=0.f,a01=0.f,a10=0.f,a11=0.f;
    for (int s=0;s<4;s++) {
        const float* Wp=g_Wm[s]; const float* Cp=g_Csol[s];
        for (int kb=0;kb<N;kb+=32) {
            __syncthreads();
            #pragma unroll
            for(int i=0;i<32;i+=8){
                Wa[lr+i][lc]=Wp[(rb+lr+i)*N+kb+lc];
                Cb[lr+i][lc]=Cp[(cb+lr+i)*N+kb+lc];
            }
            __syncthreads();
            #pragma unroll
            for (int kk=0;kk<32;kk++) {
                float w0=Wa[ty][kk], w1=Wa[ty+16][kk];
                float c0=Cb[tx][kk], c1=Cb[tx+16][kk];
                a00=fmaf(w0,c0,a00); a01=fmaf(w0,c1,a01);
                a10=fmaf(w1,c0,a10); a11=fmaf(w1,c1,a11);
            }
        }
    }
    g_R[(rb+ty   )*N+cb+tx   ]=a00;
    g_R[(rb+ty   )*N+cb+tx+16]=a01;
    g_R[(rb+ty+16)*N+cb+tx   ]=a10;
    g_R[(rb+ty+16)*N+cb+tx+16]=a11;
}

// ---------- 8. row sums ----------
__global__ void k_rowsum() {
    int i=blockIdx.x, t=threadIdx.x;
    float v=fmaxf(g_R[i*N+t],0.f);
    #pragma unroll
    for(int o=16;o;o>>=1) v+=__shfl_down_sync(~0u,v,o);
    __shared__ float sr[8];
    if(!(t&31)) sr[t>>5]=v;
    __syncthreads();
    if(t==0){ float s0=0.f;
        #pragma unroll
        for(int w=0;w<8;w++) s0+=sr[w];
        g_denum[i]=0.25f*s0+(float)N*EPS; }
}

// ---------- 9. loss ----------
__global__ void k_loss(float* __restrict__ out) {
    int t=threadIdx.x;
    float est=fmaxf(0.25f*(g_xnum[0][t]+g_xnum[1][t]+g_xnum[2][t]+g_xnum[3][t]),0.f)+EPS;
    float v=logf(g_denum[t])+logf(est);
    #pragma unroll
    for(int o=16;o;o>>=1) v+=__shfl_down_sync(~0u,v,o);
    __shared__ float sr[8];
    if(!(t&31)) sr[t>>5]=v;
    __syncthreads();
    if(t==0){ float s0=0.f;
        #pragma unroll
        for(int w=0;w<8;w++) s0+=sr[w];
        out[0]=s0; }
}

extern "C" void kernel_launch(void* const* d_in, const int* in_sizes, int n_in,
                              void* d_out, int out_size) {
    const float* z1=(const float*)d_in[0];
    const float* z2=(const float*)d_in[1];
    const int*   p1=(const int*)d_in[2];
    const int*   p2=(const int*)d_in[3];
    float* out=(float*)d_out;

    k_gather<<<N,128>>>(z1,z2,p1,p2);
    k_dist<<<dim3(8,8,5),dim3(32,32)>>>(z1,z2);
    k_build<<<dim3(N,4),N>>>();

    k_panel<<<8,512>>>(0);
    k_syrk<<<dim3(6,6,8),256>>>(0);
    k_panel<<<8,512>>>(64);
    k_syrk<<<dim3(4,4,8),256>>>(64);
    k_panel<<<8,512>>>(128);
    k_syrk<<<dim3(2,2,8),256>>>(128);
    k_panel<<<8,512>>>(192);

    k_transpose<<<dim3(8,8,8),dim3(32,8)>>>();
    k_trsm<<<dim3(33,4),256>>>();
    k_gemmR<<<dim3(8,8),256>>>();
    k_rowsum<<<N,N>>>();
    k_loss<<<1,N>>>(out);
}